// round 7
// baseline (speedup 1.0000x reference)
#include <cuda_runtime.h>
#include <math.h>

// Problem constants (fixed by the reference).
#define DD   128
#define HH   8
#define BB   8
#define SS   4096
#define EPSF 1e-8f
#define TB   16           // tokens per warp-task
#define RSTRIDE 129       // padded R row stride: conflict-free row & column scalar reads
#define XSTRIDE 20        // xs row stride (floats): 80B rows, 16B aligned for LDS.128
#define WPB  16           // warps per block (one big block per SM)
#define NTHREAD 512
#define NBLOCK  148

#define SMEM_FLOATS (128*RSTRIDE + WPB*128*XSTRIDE)   // 16512 + 40960 = 57472 -> 229888 B

// Work-stealing counters (reset each launch by reset_kernel; graph-safe, no allocs).
__device__ unsigned int g_ctr[2];

__global__ void reset_kernel() { g_ctr[0] = 0; g_ctr[1] = 0; }

// ---------------- Blackwell packed-fp32 helpers ----------------
__device__ __forceinline__ unsigned long long pack2(float x) {
    unsigned long long d; unsigned int u = __float_as_uint(x);
    asm("mov.b64 %0, {%1, %1};" : "=l"(d) : "r"(u));
    return d;
}
__device__ __forceinline__ void fma2(unsigned long long& d, unsigned long long a, unsigned long long b) {
    asm("fma.rn.f32x2 %0, %1, %2, %0;" : "+l"(d) : "l"(a), "l"(b));
}
__device__ __forceinline__ float2 unpack2(unsigned long long p) {
    unsigned int lo, hi;
    asm("mov.b64 {%0, %1}, %2;" : "=r"(lo), "=r"(hi) : "l"(p));
    return make_float2(__uint_as_float(lo), __uint_as_float(hi));
}
__device__ __forceinline__ float warp_sum(float v) {
#pragma unroll
    for (int o = 16; o; o >>= 1) v += __shfl_xor_sync(0xffffffffu, v, o);
    return v;
}
__device__ __forceinline__ unsigned int next_task(int which, int lane) {
    unsigned int t;
    if (lane == 0) t = atomicAdd(&g_ctr[which], 1u);
    return __shfl_sync(0xffffffffu, t, 0);
}

// 128-long matvec: 4 rows/cols (lane L owns L,L+32,L+64,L+96) x 16 tokens -> 32 packed accs.
// acc[k*8+p] = (y[L+32k][2p], y[L+32k][2p+1]).  RSTEP=1: row mode; RSTEP=RSTRIDE: column mode.
template <int RSTEP>
__device__ __forceinline__ void matvec128(const float* __restrict__ r0, const float* __restrict__ r1,
                                          const float* __restrict__ r2, const float* __restrict__ r3,
                                          const float* __restrict__ xs, unsigned long long acc[32]) {
#pragma unroll
    for (int p = 0; p < 32; p++) acc[p] = 0ull;
#pragma unroll 4
    for (int j = 0; j < 128; j++) {
        unsigned long long rr0 = pack2(r0[j * RSTEP]);
        unsigned long long rr1 = pack2(r1[j * RSTEP]);
        unsigned long long rr2 = pack2(r2[j * RSTEP]);
        unsigned long long rr3 = pack2(r3[j * RSTEP]);
        // 4x broadcast LDS.128: token pairs (0..7), (8..15)
        ulonglong2 pa = *(const ulonglong2*)(xs + j * XSTRIDE);
        ulonglong2 pb = *(const ulonglong2*)(xs + j * XSTRIDE + 4);
        ulonglong2 pc = *(const ulonglong2*)(xs + j * XSTRIDE + 8);
        ulonglong2 pd = *(const ulonglong2*)(xs + j * XSTRIDE + 12);
        fma2(acc[0], rr0, pa.x); fma2(acc[1], rr0, pa.y); fma2(acc[2], rr0, pb.x); fma2(acc[3], rr0, pb.y);
        fma2(acc[4], rr0, pc.x); fma2(acc[5], rr0, pc.y); fma2(acc[6], rr0, pd.x); fma2(acc[7], rr0, pd.y);
        fma2(acc[8], rr1, pa.x); fma2(acc[9], rr1, pa.y); fma2(acc[10], rr1, pb.x); fma2(acc[11], rr1, pb.y);
        fma2(acc[12], rr1, pc.x); fma2(acc[13], rr1, pc.y); fma2(acc[14], rr1, pd.x); fma2(acc[15], rr1, pd.y);
        fma2(acc[16], rr2, pa.x); fma2(acc[17], rr2, pa.y); fma2(acc[18], rr2, pb.x); fma2(acc[19], rr2, pb.y);
        fma2(acc[20], rr2, pc.x); fma2(acc[21], rr2, pc.y); fma2(acc[22], rr2, pd.x); fma2(acc[23], rr2, pd.y);
        fma2(acc[24], rr3, pa.x); fma2(acc[25], rr3, pa.y); fma2(acc[26], rr3, pb.x); fma2(acc[27], rr3, pb.y);
        fma2(acc[28], rr3, pc.x); fma2(acc[29], rr3, pc.y); fma2(acc[30], rr3, pd.x); fma2(acc[31], rr3, pd.y);
    }
}

__device__ __forceinline__ void stage_R(float* Rs, const float* __restrict__ R, int tid) {
#pragma unroll 4
    for (int idx = tid; idx < 128 * 128; idx += NTHREAD) {
        int i = idx >> 7, j = idx & 127;
        Rs[i * RSTRIDE + j] = R[idx];
    }
}

// ---------------- Phase 1: anchor head (ResidualQuant) ----------------
__global__ void __launch_bounds__(NTHREAD, 1)
anchor_kernel(const float* __restrict__ kv, const float* __restrict__ Ra,
              const float* __restrict__ cba, float* __restrict__ out, int ntask) {
    extern __shared__ float sm[];
    float* Rs = sm;
    const int tid = threadIdx.x;
    const int w = tid >> 5, L = tid & 31;
    float* xs = sm + 128 * RSTRIDE + w * (128 * XSTRIDE);

    stage_R(Rs, Ra, tid);
    const float c0 = cba[0], c1 = cba[1], c2 = cba[2], c3 = cba[3];
    const float t0 = 0.5f * (c0 + c1), t1 = 0.5f * (c1 + c2), t2 = 0.5f * (c2 + c3);
    __syncthreads();

    const float* rr0 = Rs + (L +  0) * RSTRIDE;
    const float* rr1 = Rs + (L + 32) * RSTRIDE;
    const float* rr2 = Rs + (L + 64) * RSTRIDE;
    const float* rr3 = Rs + (L + 96) * RSTRIDE;
    const float* rc0 = Rs + (L +  0);
    const float* rc1 = Rs + (L + 32);
    const float* rc2 = Rs + (L + 64);
    const float* rc3 = Rs + (L + 96);

    for (;;) {
        unsigned int task = next_task(0, L);
        if (task >= (unsigned)ntask) break;
        const int base = (int)task * TB;   // token = b*SS + s

        // ---- stage x; per-token ssq accumulated locally, reduced in one batch ----
        float sq[TB], nn[TB], inv[TB];
#pragma unroll
        for (int t = 0; t < TB; t++) {
            int tok = base + t;
            int b = tok >> 12, s = tok & (SS - 1);
            unsigned int o = ((unsigned)(b * HH) * SS + (unsigned)s) * DD;
            float ssq = 0.f;
#pragma unroll
            for (int c = 0; c < 4; c++) {
                int j = L + 32 * c;
                float x = kv[o + j];
                xs[j * XSTRIDE + t] = x;
                ssq += x * x;
            }
            sq[t] = ssq;
        }
#pragma unroll
        for (int t = 0; t < TB; t++) {             // 16 independent shfl chains (ILP)
            float tot = warp_sum(sq[t]);
            nn[t] = sqrtf(tot);
            inv[t] = 1.0f / (nn[t] + EPSF);
        }
        __syncwarp();

        unsigned long long acc[32];
        matvec128<1>(rr0, rr1, rr2, rr3, xs, acc);

        // ---- pass A: quantize, accumulate |res| per token ----
        float A[TB];
#pragma unroll
        for (int t = 0; t < TB; t++) A[t] = 0.f;
#pragma unroll
        for (int k = 0; k < 4; k++) {
#pragma unroll
            for (int p = 0; p < 8; p++) {
                float2 y = unpack2(acc[k * 8 + p]);
                float y0 = y.x * inv[2 * p], y1 = y.y * inv[2 * p + 1];
                float q0 = (y0 <= t1) ? ((y0 <= t0) ? c0 : c1) : ((y0 <= t2) ? c2 : c3);
                float q1 = (y1 <= t1) ? ((y1 <= t0) ? c0 : c1) : ((y1 <= t2) ? c2 : c3);
                A[2 * p]     += fabsf(y0 - q0);
                A[2 * p + 1] += fabsf(y1 - q1);
            }
        }
#pragma unroll
        for (int t = 0; t < TB; t++) A[t] = warp_sum(A[t]) * (1.0f / 128.0f);  // alpha

        __syncwarp();   // matvec1 done reading xs warp-wide

        // ---- pass B: yhat -> xs ----
#pragma unroll
        for (int k = 0; k < 4; k++) {
            int i = L + 32 * k;
#pragma unroll
            for (int p = 0; p < 8; p++) {
                float2 y = unpack2(acc[k * 8 + p]);
#pragma unroll
                for (int h = 0; h < 2; h++) {
                    int t = 2 * p + h;
                    float yy = (h ? y.y : y.x) * inv[t];
                    float q = (yy <= t1) ? ((yy <= t0) ? c0 : c1) : ((yy <= t2) ? c2 : c3);
                    float res = yy - q;
                    float sg = (res > 0.f) ? 1.f : ((res < 0.f) ? -1.f : 0.f);
                    xs[i * XSTRIDE + t] = q + A[t] * sg;
                }
            }
        }
        __syncwarp();

        matvec128<RSTRIDE>(rc0, rc1, rc2, rc3, xs, acc);

        // ---- output: out = rec * norm (offsets recomputed; coalesced) ----
#pragma unroll
        for (int t = 0; t < TB; t++) {
            int tok = base + t;
            int b = tok >> 12, s = tok & (SS - 1);
            unsigned int o = ((unsigned)(b * HH) * SS + (unsigned)s) * DD;
            int p = t >> 1;
#pragma unroll
            for (int k = 0; k < 4; k++) {
                float2 r = unpack2(acc[k * 8 + p]);
                float rv = (t & 1) ? r.y : r.x;
                out[o + L + 32 * k] = rv * nn[t];
            }
        }
        __syncwarp();   // protect xs before next task
    }
}

// ---------------- Phase 2: delta heads (PolarQuant vs anchor recon) ----------------
__global__ void __launch_bounds__(NTHREAD, 1)
delta_kernel(const float* __restrict__ kv, const float* __restrict__ Rd,
             const float* __restrict__ cbd, float* __restrict__ out, int ntask) {
    extern __shared__ float sm[];
    float* Rs = sm;
    const int tid = threadIdx.x;
    const int w = tid >> 5, L = tid & 31;
    float* xs = sm + 128 * RSTRIDE + w * (128 * XSTRIDE);

    stage_R(Rs, Rd, tid);
    const float c0 = cbd[0], c1 = cbd[1];
    const float mid = 0.5f * (c0 + c1);
    __syncthreads();

    const float* rr0 = Rs + (L +  0) * RSTRIDE;
    const float* rr1 = Rs + (L + 32) * RSTRIDE;
    const float* rr2 = Rs + (L + 64) * RSTRIDE;
    const float* rr3 = Rs + (L + 96) * RSTRIDE;
    const float* rc0 = Rs + (L +  0);
    const float* rc1 = Rs + (L + 32);
    const float* rc2 = Rs + (L + 64);
    const float* rc3 = Rs + (L + 96);

    for (;;) {
        unsigned int task = next_task(1, L);
        if (task >= (unsigned)ntask) break;
        const int base = (int)task * TB;   // u = (b*(HH-1)+(h-1))*SS + s

        float sq[TB], nn[TB], inv[TB];
#pragma unroll
        for (int t = 0; t < TB; t++) {
            int u = base + t;
            int b = u / ((HH - 1) * SS);
            int rem = u - b * ((HH - 1) * SS);
            int h = (rem >> 12) + 1;
            int s = rem & (SS - 1);
            unsigned int ko  = ((unsigned)(b * HH + h) * SS + (unsigned)s) * DD;
            unsigned int aoo = ((unsigned)(b * HH) * SS + (unsigned)s) * DD;
            float ssq = 0.f;
#pragma unroll
            for (int c = 0; c < 4; c++) {
                int j = L + 32 * c;
                float x = kv[ko + j] - out[aoo + j];
                xs[j * XSTRIDE + t] = x;
                ssq += x * x;
            }
            sq[t] = ssq;
        }
#pragma unroll
        for (int t = 0; t < TB; t++) {
            float tot = warp_sum(sq[t]);
            nn[t] = sqrtf(tot);
            inv[t] = 1.0f / (nn[t] + EPSF);
        }
        __syncwarp();

        unsigned long long acc[32];
        matvec128<1>(rr0, rr1, rr2, rr3, xs, acc);

        __syncwarp();   // all lanes done reading xs

        // ---- 1-bit polar quantize -> xs ----
#pragma unroll
        for (int k = 0; k < 4; k++) {
            int i = L + 32 * k;
#pragma unroll
            for (int p = 0; p < 8; p++) {
                float2 y = unpack2(acc[k * 8 + p]);
                float y0 = y.x * inv[2 * p], y1 = y.y * inv[2 * p + 1];
                xs[i * XSTRIDE + 2 * p]     = (y0 <= mid) ? c0 : c1;
                xs[i * XSTRIDE + 2 * p + 1] = (y1 <= mid) ? c0 : c1;
            }
        }
        __syncwarp();

        matvec128<RSTRIDE>(rc0, rc1, rc2, rc3, xs, acc);

        // ---- output: out = anchor + rec * norm (offsets recomputed; coalesced) ----
#pragma unroll
        for (int t = 0; t < TB; t++) {
            int u = base + t;
            int b = u / ((HH - 1) * SS);
            int rem = u - b * ((HH - 1) * SS);
            int h = (rem >> 12) + 1;
            int s = rem & (SS - 1);
            unsigned int ko  = ((unsigned)(b * HH + h) * SS + (unsigned)s) * DD;
            unsigned int aoo = ((unsigned)(b * HH) * SS + (unsigned)s) * DD;
            int p = t >> 1;
#pragma unroll
            for (int k = 0; k < 4; k++) {
                float2 r = unpack2(acc[k * 8 + p]);
                float rv = (t & 1) ? r.y : r.x;
                int j = L + 32 * k;
                out[ko + j] = out[aoo + j] + rv * nn[t];
            }
        }
        __syncwarp();
    }
}

extern "C" void kernel_launch(void* const* d_in, const int* in_sizes, int n_in,
                              void* d_out, int out_size) {
    const float* kv  = (const float*)d_in[0];
    const float* Ra  = (const float*)d_in[1];
    const float* cba = (const float*)d_in[2];
    const float* Rd  = (const float*)d_in[3];
    const float* cbd = (const float*)d_in[4];
    float* out = (float*)d_out;

    const int smem_bytes = SMEM_FLOATS * (int)sizeof(float);  // 229888
    cudaFuncSetAttribute(anchor_kernel, cudaFuncAttributeMaxDynamicSharedMemorySize, smem_bytes);
    cudaFuncSetAttribute(delta_kernel,  cudaFuncAttributeMaxDynamicSharedMemorySize, smem_bytes);

    const int n_anchor_task = (BB * SS) / TB;             // 2048
    const int n_delta_task  = (BB * (HH - 1) * SS) / TB;  // 14336

    reset_kernel<<<1, 1>>>();
    anchor_kernel<<<NBLOCK, NTHREAD, smem_bytes>>>(kv, Ra, cba, out, n_anchor_task);
    delta_kernel <<<NBLOCK, NTHREAD, smem_bytes>>>(kv, Rd, cbd, out, n_delta_task);
}

// round 8
// speedup vs baseline: 1.0947x; 1.0947x over previous
#include <cuda_runtime.h>
#include <math.h>

// Problem constants (fixed by the reference).
#define DD   128
#define HH   8
#define BB   8
#define SS   4096
#define EPSF 1e-8f
#define TB   8            // tokens per matvec batch
#define RSTRIDE 129       // padded R row stride: conflict-free row & column scalar reads
#define XSTRIDE 12        // xs row stride (floats): 48B rows, 16B aligned for LDS.128
#define WPB  16           // warps per block (one block per SM)
#define NTHREAD 512
#define NBLOCK  148

// Per-warp smem (floats): xs 128*12 = 1536, as 8*128 = 1024
#define WFLOATS_D (128*XSTRIDE + TB*DD)
#define WFLOATS_A (128*XSTRIDE)
#define SMEM_FLOATS_D (128*RSTRIDE + WPB*WFLOATS_D)   // 57472 -> 229888 B
#define SMEM_FLOATS_A (128*RSTRIDE + WPB*WFLOATS_A)   // 41088 -> 164352 B

// Work-stealing counters (reset each launch; graph-safe, no allocs).
__device__ unsigned int g_ctr[2];
__global__ void reset_kernel() { if (threadIdx.x < 2) g_ctr[threadIdx.x] = 0; }

// ---------------- Blackwell packed-fp32 helpers ----------------
__device__ __forceinline__ unsigned long long pack2(float x) {
    unsigned long long d; unsigned int u = __float_as_uint(x);
    asm("mov.b64 %0, {%1, %1};" : "=l"(d) : "r"(u));
    return d;
}
__device__ __forceinline__ void fma2(unsigned long long& d, unsigned long long a, unsigned long long b) {
    asm("fma.rn.f32x2 %0, %1, %2, %0;" : "+l"(d) : "l"(a), "l"(b));
}
__device__ __forceinline__ float2 unpack2(unsigned long long p) {
    unsigned int lo, hi;
    asm("mov.b64 {%0, %1}, %2;" : "=r"(lo), "=r"(hi) : "l"(p));
    return make_float2(__uint_as_float(lo), __uint_as_float(hi));
}
__device__ __forceinline__ float warp_sum(float v) {
#pragma unroll
    for (int o = 16; o; o >>= 1) v += __shfl_xor_sync(0xffffffffu, v, o);
    return v;
}
__device__ __forceinline__ unsigned int next_task(int which, int lane) {
    unsigned int t;
    if (lane == 0) t = atomicAdd(&g_ctr[which], 1u);
    return __shfl_sync(0xffffffffu, t, 0);
}

// 128-long matvec: 4 rows/cols (lane L owns L,L+32,L+64,L+96) x 8 tokens -> 16 packed accs.
// acc[k*4+p] = (y[L+32k][2p], y[L+32k][2p+1]).  RSTEP=1: row mode; RSTEP=RSTRIDE: column mode.
template <int RSTEP>
__device__ __forceinline__ void matvec128(const float* __restrict__ r0, const float* __restrict__ r1,
                                          const float* __restrict__ r2, const float* __restrict__ r3,
                                          const float* __restrict__ xs, unsigned long long acc[16]) {
#pragma unroll
    for (int p = 0; p < 16; p++) acc[p] = 0ull;
#pragma unroll 8
    for (int j = 0; j < 128; j++) {
        unsigned long long rr0 = pack2(r0[j * RSTEP]);
        unsigned long long rr1 = pack2(r1[j * RSTEP]);
        unsigned long long rr2 = pack2(r2[j * RSTEP]);
        unsigned long long rr3 = pack2(r3[j * RSTEP]);
        ulonglong2 pa = *(const ulonglong2*)(xs + j * XSTRIDE);      // tokens 0..3 (broadcast)
        ulonglong2 pb = *(const ulonglong2*)(xs + j * XSTRIDE + 4);  // tokens 4..7
        fma2(acc[0],  rr0, pa.x); fma2(acc[1],  rr0, pa.y); fma2(acc[2],  rr0, pb.x); fma2(acc[3],  rr0, pb.y);
        fma2(acc[4],  rr1, pa.x); fma2(acc[5],  rr1, pa.y); fma2(acc[6],  rr1, pb.x); fma2(acc[7],  rr1, pb.y);
        fma2(acc[8],  rr2, pa.x); fma2(acc[9],  rr2, pa.y); fma2(acc[10], rr2, pb.x); fma2(acc[11], rr2, pb.y);
        fma2(acc[12], rr3, pa.x); fma2(acc[13], rr3, pa.y); fma2(acc[14], rr3, pb.x); fma2(acc[15], rr3, pb.y);
    }
}

__device__ __forceinline__ void stage_R(float* Rs, const float* __restrict__ R, int tid) {
#pragma unroll 4
    for (int idx = tid; idx < 128 * 128; idx += NTHREAD) {
        int i = idx >> 7, j = idx & 127;
        Rs[i * RSTRIDE + j] = R[idx];
    }
}

// ---------------- Phase 1: anchor head (ResidualQuant) ----------------
__global__ void __launch_bounds__(NTHREAD, 1)
anchor_kernel(const float* __restrict__ kv, const float* __restrict__ Ra,
              const float* __restrict__ cba, float* __restrict__ out, int ntask) {
    extern __shared__ float sm[];
    float* Rs = sm;
    const int tid = threadIdx.x;
    const int w = tid >> 5, L = tid & 31;
    float* xs = sm + 128 * RSTRIDE + w * WFLOATS_A;

    stage_R(Rs, Ra, tid);
    const float c0 = cba[0], c1 = cba[1], c2 = cba[2], c3 = cba[3];
    const float t0 = 0.5f * (c0 + c1), t1 = 0.5f * (c1 + c2), t2 = 0.5f * (c2 + c3);
    __syncthreads();

    const float* rr0 = Rs + (L +  0) * RSTRIDE;
    const float* rr1 = Rs + (L + 32) * RSTRIDE;
    const float* rr2 = Rs + (L + 64) * RSTRIDE;
    const float* rr3 = Rs + (L + 96) * RSTRIDE;
    const float* rc0 = Rs + (L +  0);
    const float* rc1 = Rs + (L + 32);
    const float* rc2 = Rs + (L + 64);
    const float* rc3 = Rs + (L + 96);

    for (;;) {
        unsigned int task = next_task(0, L);
        if (task >= (unsigned)ntask) break;
        // task -> (b, sbase): 8 contiguous s within one b, head 0
        const int b = (int)(task >> 9);
        const int sbase = ((int)task & 511) * TB;
        const unsigned int base = ((unsigned)(b * HH) * SS + (unsigned)sbase) * DD;

        // ---- stage x (LDG.128, lane owns j=4L..4L+3), batched reductions ----
        float sq[TB], nn[TB], inv[TB];
#pragma unroll
        for (int t = 0; t < TB; t++) {
            float4 v = *(const float4*)(kv + base + t * DD + 4 * L);
            xs[(4 * L + 0) * XSTRIDE + t] = v.x;
            xs[(4 * L + 1) * XSTRIDE + t] = v.y;
            xs[(4 * L + 2) * XSTRIDE + t] = v.z;
            xs[(4 * L + 3) * XSTRIDE + t] = v.w;
            sq[t] = v.x * v.x + v.y * v.y + v.z * v.z + v.w * v.w;
        }
#pragma unroll
        for (int t = 0; t < TB; t++) {     // 8 independent shfl trees (ILP)
            float tot = warp_sum(sq[t]);
            nn[t] = sqrtf(tot);
            inv[t] = 1.0f / (nn[t] + EPSF);
        }
        __syncwarp();

        unsigned long long acc[16];
        matvec128<1>(rr0, rr1, rr2, rr3, xs, acc);

        // ---- pass A: quantize + |res| accumulation ----
        float A[TB];
#pragma unroll
        for (int t = 0; t < TB; t++) A[t] = 0.f;
#pragma unroll
        for (int k = 0; k < 4; k++) {
#pragma unroll
            for (int p = 0; p < 4; p++) {
                float2 y = unpack2(acc[k * 4 + p]);
                float y0 = y.x * inv[2 * p], y1 = y.y * inv[2 * p + 1];
                float q0 = (y0 <= t1) ? ((y0 <= t0) ? c0 : c1) : ((y0 <= t2) ? c2 : c3);
                float q1 = (y1 <= t1) ? ((y1 <= t0) ? c0 : c1) : ((y1 <= t2) ? c2 : c3);
                A[2 * p]     += fabsf(y0 - q0);
                A[2 * p + 1] += fabsf(y1 - q1);
            }
        }
#pragma unroll
        for (int t = 0; t < TB; t++) A[t] = warp_sum(A[t]) * (1.0f / 128.0f);  // alpha

        __syncwarp();   // matvec1 done reading xs warp-wide

        // ---- pass B: yhat -> xs ----
#pragma unroll
        for (int k = 0; k < 4; k++) {
            int i = L + 32 * k;
#pragma unroll
            for (int p = 0; p < 4; p++) {
                float2 y = unpack2(acc[k * 4 + p]);
#pragma unroll
                for (int h = 0; h < 2; h++) {
                    int t = 2 * p + h;
                    float yy = (h ? y.y : y.x) * inv[t];
                    float q = (yy <= t1) ? ((yy <= t0) ? c0 : c1) : ((yy <= t2) ? c2 : c3);
                    float res = yy - q;
                    float sg = (res > 0.f) ? 1.f : ((res < 0.f) ? -1.f : 0.f);
                    xs[i * XSTRIDE + t] = q + A[t] * sg;
                }
            }
        }
        __syncwarp();

        matvec128<RSTRIDE>(rc0, rc1, rc2, rc3, xs, acc);

        // ---- output: out = rec * norm ----
#pragma unroll
        for (int t = 0; t < TB; t++) {
            int p = t >> 1;
#pragma unroll
            for (int k = 0; k < 4; k++) {
                float2 r = unpack2(acc[k * 4 + p]);
                float rv = (t & 1) ? r.y : r.x;
                out[base + t * DD + L + 32 * k] = rv * nn[t];
            }
        }
        __syncwarp();   // protect xs before next task
    }
}

// ---------------- Phase 2: delta heads (PolarQuant vs anchor recon) ----------------
// Supertask: one (b, 8-token s-chunk) covering all 7 delta heads; anchor recon
// cached in per-warp smem and reused 7x (prologue subtract + epilogue add).
__global__ void __launch_bounds__(NTHREAD, 1)
delta_kernel(const float* __restrict__ kv, const float* __restrict__ Rd,
             const float* __restrict__ cbd, float* __restrict__ out, int ntask) {
    extern __shared__ float sm[];
    float* Rs = sm;
    const int tid = threadIdx.x;
    const int w = tid >> 5, L = tid & 31;
    float* xs = sm + 128 * RSTRIDE + w * WFLOATS_D;
    float* as = xs + 128 * XSTRIDE;          // [t][j], stride 128 (16B aligned)

    stage_R(Rs, Rd, tid);
    const float c0 = cbd[0], c1 = cbd[1];
    const float mid = 0.5f * (c0 + c1);
    __syncthreads();

    const float* rr0 = Rs + (L +  0) * RSTRIDE;
    const float* rr1 = Rs + (L + 32) * RSTRIDE;
    const float* rr2 = Rs + (L + 64) * RSTRIDE;
    const float* rr3 = Rs + (L + 96) * RSTRIDE;
    const float* rc0 = Rs + (L +  0);
    const float* rc1 = Rs + (L + 32);
    const float* rc2 = Rs + (L + 64);
    const float* rc3 = Rs + (L + 96);

    for (;;) {
        unsigned int task = next_task(1, L);
        if (task >= (unsigned)ntask) break;
        const int b = (int)(task >> 9);
        const int sbase = ((int)task & 511) * TB;
        const unsigned int abase = ((unsigned)(b * HH) * SS + (unsigned)sbase) * DD;

        // ---- stage anchor recon once for all 7 heads (LDG.128 -> STS.128) ----
#pragma unroll
        for (int t = 0; t < TB; t++) {
            float4 v = *(const float4*)(out + abase + t * DD + 4 * L);
            *(float4*)(as + t * DD + 4 * L) = v;
        }
        __syncwarp();

        for (int h = 1; h < HH; h++) {
            const unsigned int kbase = ((unsigned)(b * HH + h) * SS + (unsigned)sbase) * DD;

            // ---- stage delta = kv - anchor (LDG.128 + LDS.128), batched reductions ----
            float sq[TB], nn[TB], inv[TB];
#pragma unroll
            for (int t = 0; t < TB; t++) {
                float4 kvv = *(const float4*)(kv + kbase + t * DD + 4 * L);
                float4 av  = *(const float4*)(as + t * DD + 4 * L);
                float x0 = kvv.x - av.x, x1 = kvv.y - av.y;
                float x2 = kvv.z - av.z, x3 = kvv.w - av.w;
                xs[(4 * L + 0) * XSTRIDE + t] = x0;
                xs[(4 * L + 1) * XSTRIDE + t] = x1;
                xs[(4 * L + 2) * XSTRIDE + t] = x2;
                xs[(4 * L + 3) * XSTRIDE + t] = x3;
                sq[t] = x0 * x0 + x1 * x1 + x2 * x2 + x3 * x3;
            }
#pragma unroll
            for (int t = 0; t < TB; t++) {
                float tot = warp_sum(sq[t]);
                nn[t] = sqrtf(tot);
                inv[t] = 1.0f / (nn[t] + EPSF);
            }
            __syncwarp();

            unsigned long long acc[16];
            matvec128<1>(rr0, rr1, rr2, rr3, xs, acc);

            __syncwarp();   // all lanes done reading xs

            // ---- 1-bit polar quantize -> xs ----
#pragma unroll
            for (int k = 0; k < 4; k++) {
                int i = L + 32 * k;
#pragma unroll
                for (int p = 0; p < 4; p++) {
                    float2 y = unpack2(acc[k * 4 + p]);
                    float y0 = y.x * inv[2 * p], y1 = y.y * inv[2 * p + 1];
                    xs[i * XSTRIDE + 2 * p]     = (y0 <= mid) ? c0 : c1;
                    xs[i * XSTRIDE + 2 * p + 1] = (y1 <= mid) ? c0 : c1;
                }
            }
            __syncwarp();

            matvec128<RSTRIDE>(rc0, rc1, rc2, rc3, xs, acc);

            // ---- output: out = anchor(smem) + rec * norm ----
#pragma unroll
            for (int t = 0; t < TB; t++) {
                int p = t >> 1;
#pragma unroll
                for (int k = 0; k < 4; k++) {
                    float2 r = unpack2(acc[k * 4 + p]);
                    float rv = (t & 1) ? r.y : r.x;
                    int j = L + 32 * k;
                    out[kbase + t * DD + j] = as[t * DD + j] + rv * nn[t];
                }
            }
            __syncwarp();   // protect xs before next head restages
        }
    }
}

extern "C" void kernel_launch(void* const* d_in, const int* in_sizes, int n_in,
                              void* d_out, int out_size) {
    const float* kv  = (const float*)d_in[0];
    const float* Ra  = (const float*)d_in[1];
    const float* cba = (const float*)d_in[2];
    const float* Rd  = (const float*)d_in[3];
    const float* cbd = (const float*)d_in[4];
    float* out = (float*)d_out;

    const int smem_a = SMEM_FLOATS_A * (int)sizeof(float);  // 164352
    const int smem_d = SMEM_FLOATS_D * (int)sizeof(float);  // 229888
    cudaFuncSetAttribute(anchor_kernel, cudaFuncAttributeMaxDynamicSharedMemorySize, smem_a);
    cudaFuncSetAttribute(delta_kernel,  cudaFuncAttributeMaxDynamicSharedMemorySize, smem_d);

    const int n_anchor_task = (BB * SS) / TB;   // 4096
    const int n_delta_task  = (BB * SS) / TB;   // 4096 supertasks (x7 heads each)

    reset_kernel<<<1, 32>>>();
    anchor_kernel<<<NBLOCK, NTHREAD, smem_a>>>(kv, Ra, cba, out, n_anchor_task);
    delta_kernel <<<NBLOCK, NTHREAD, smem_d>>>(kv, Rd, cbd, out, n_delta_task);
}

// round 9
// speedup vs baseline: 1.1425x; 1.0437x over previous
#include <cuda_runtime.h>
#include <math.h>

// Problem constants (fixed by the reference).
#define DD   128
#define HH   8
#define BB   8
#define SS   4096
#define EPSF 1e-8f
#define TBA  8            // tokens per anchor task
#define TBD  16           // tokens per delta task
#define RSTRIDE 129       // padded R row stride: conflict-free row & column scalar reads
#define XSA  12           // anchor xs row stride (8 tokens + pad, 16B-aligned rows)
#define XSD  20           // delta xs row stride (16 tokens + pad, 16B-aligned rows)
#define NTHREAD 384       // 12 warps/SM, 170-reg budget
#define NWARP   12
#define NBLOCK  148

#define SMEM_FLOATS_A (128*RSTRIDE + NWARP*128*XSA)   // 34944 -> 139776 B
#define SMEM_FLOATS_D (128*RSTRIDE + NWARP*128*XSD)   // 47232 -> 188928 B

// Work-stealing counters (reset each launch; graph-safe, no allocs).
__device__ unsigned int g_ctr[2];
__global__ void reset_kernel() { if (threadIdx.x < 2) g_ctr[threadIdx.x] = 0; }

// ---------------- Blackwell packed-fp32 helpers ----------------
__device__ __forceinline__ unsigned long long pack2(float x) {
    unsigned long long d; unsigned int u = __float_as_uint(x);
    asm("mov.b64 %0, {%1, %1};" : "=l"(d) : "r"(u));
    return d;
}
__device__ __forceinline__ void fma2(unsigned long long& d, unsigned long long a, unsigned long long b) {
    asm("fma.rn.f32x2 %0, %1, %2, %0;" : "+l"(d) : "l"(a), "l"(b));
}
__device__ __forceinline__ float2 unpack2(unsigned long long p) {
    unsigned int lo, hi;
    asm("mov.b64 {%0, %1}, %2;" : "=r"(lo), "=r"(hi) : "l"(p));
    return make_float2(__uint_as_float(lo), __uint_as_float(hi));
}
__device__ __forceinline__ float warp_sum(float v) {
#pragma unroll
    for (int o = 16; o; o >>= 1) v += __shfl_xor_sync(0xffffffffu, v, o);
    return v;
}
__device__ __forceinline__ unsigned int next_task(int which, int lane) {
    unsigned int t;
    if (lane == 0) t = atomicAdd(&g_ctr[which], 1u);
    return __shfl_sync(0xffffffffu, t, 0);
}

// ---- matvec, TB=8: 4 rows/cols x 8 tokens -> 16 packed accs ----
template <int RSTEP>
__device__ __forceinline__ void matvec8(const float* __restrict__ r0, const float* __restrict__ r1,
                                        const float* __restrict__ r2, const float* __restrict__ r3,
                                        const float* __restrict__ xs, unsigned long long acc[16]) {
#pragma unroll
    for (int p = 0; p < 16; p++) acc[p] = 0ull;
#pragma unroll 8
    for (int j = 0; j < 128; j++) {
        unsigned long long rr0 = pack2(r0[j * RSTEP]);
        unsigned long long rr1 = pack2(r1[j * RSTEP]);
        unsigned long long rr2 = pack2(r2[j * RSTEP]);
        unsigned long long rr3 = pack2(r3[j * RSTEP]);
        ulonglong2 pa = *(const ulonglong2*)(xs + j * XSA);
        ulonglong2 pb = *(const ulonglong2*)(xs + j * XSA + 4);
        fma2(acc[0],  rr0, pa.x); fma2(acc[1],  rr0, pa.y); fma2(acc[2],  rr0, pb.x); fma2(acc[3],  rr0, pb.y);
        fma2(acc[4],  rr1, pa.x); fma2(acc[5],  rr1, pa.y); fma2(acc[6],  rr1, pb.x); fma2(acc[7],  rr1, pb.y);
        fma2(acc[8],  rr2, pa.x); fma2(acc[9],  rr2, pa.y); fma2(acc[10], rr2, pb.x); fma2(acc[11], rr2, pb.y);
        fma2(acc[12], rr3, pa.x); fma2(acc[13], rr3, pa.y); fma2(acc[14], rr3, pb.x); fma2(acc[15], rr3, pb.y);
    }
}

// ---- matvec, TB=16: 4 rows/cols x 16 tokens -> 32 packed accs ----
template <int RSTEP>
__device__ __forceinline__ void matvec16(const float* __restrict__ r0, const float* __restrict__ r1,
                                         const float* __restrict__ r2, const float* __restrict__ r3,
                                         const float* __restrict__ xs, unsigned long long acc[32]) {
#pragma unroll
    for (int p = 0; p < 32; p++) acc[p] = 0ull;
#pragma unroll 4
    for (int j = 0; j < 128; j++) {
        unsigned long long rr0 = pack2(r0[j * RSTEP]);
        unsigned long long rr1 = pack2(r1[j * RSTEP]);
        unsigned long long rr2 = pack2(r2[j * RSTEP]);
        unsigned long long rr3 = pack2(r3[j * RSTEP]);
        ulonglong2 pa = *(const ulonglong2*)(xs + j * XSD);
        ulonglong2 pb = *(const ulonglong2*)(xs + j * XSD + 4);
        ulonglong2 pc = *(const ulonglong2*)(xs + j * XSD + 8);
        ulonglong2 pd = *(const ulonglong2*)(xs + j * XSD + 12);
        fma2(acc[0], rr0, pa.x); fma2(acc[1], rr0, pa.y); fma2(acc[2], rr0, pb.x); fma2(acc[3], rr0, pb.y);
        fma2(acc[4], rr0, pc.x); fma2(acc[5], rr0, pc.y); fma2(acc[6], rr0, pd.x); fma2(acc[7], rr0, pd.y);
        fma2(acc[8], rr1, pa.x); fma2(acc[9], rr1, pa.y); fma2(acc[10], rr1, pb.x); fma2(acc[11], rr1, pb.y);
        fma2(acc[12], rr1, pc.x); fma2(acc[13], rr1, pc.y); fma2(acc[14], rr1, pd.x); fma2(acc[15], rr1, pd.y);
        fma2(acc[16], rr2, pa.x); fma2(acc[17], rr2, pa.y); fma2(acc[18], rr2, pb.x); fma2(acc[19], rr2, pb.y);
        fma2(acc[20], rr2, pc.x); fma2(acc[21], rr2, pc.y); fma2(acc[22], rr2, pd.x); fma2(acc[23], rr2, pd.y);
        fma2(acc[24], rr3, pa.x); fma2(acc[25], rr3, pa.y); fma2(acc[26], rr3, pb.x); fma2(acc[27], rr3, pb.y);
        fma2(acc[28], rr3, pc.x); fma2(acc[29], rr3, pc.y); fma2(acc[30], rr3, pd.x); fma2(acc[31], rr3, pd.y);
    }
}

__device__ __forceinline__ void stage_R(float* Rs, const float* __restrict__ R, int tid) {
#pragma unroll 4
    for (int idx = tid; idx < 128 * 128; idx += NTHREAD) {
        int i = idx >> 7, j = idx & 127;
        Rs[i * RSTRIDE + j] = R[idx];
    }
}

// ---------------- Phase 1: anchor head (ResidualQuant), TB=8 ----------------
__global__ void __launch_bounds__(NTHREAD, 1)
anchor_kernel(const float* __restrict__ kv, const float* __restrict__ Ra,
              const float* __restrict__ cba, float* __restrict__ out, int ntask) {
    extern __shared__ float sm[];
    float* Rs = sm;
    const int tid = threadIdx.x;
    const int w = tid >> 5, L = tid & 31;
    float* xs = sm + 128 * RSTRIDE + w * (128 * XSA);

    stage_R(Rs, Ra, tid);
    const float c0 = cba[0], c1 = cba[1], c2 = cba[2], c3 = cba[3];
    const float t0 = 0.5f * (c0 + c1), t1 = 0.5f * (c1 + c2), t2 = 0.5f * (c2 + c3);
    __syncthreads();

    const float* rr0 = Rs + (L +  0) * RSTRIDE;
    const float* rr1 = Rs + (L + 32) * RSTRIDE;
    const float* rr2 = Rs + (L + 64) * RSTRIDE;
    const float* rr3 = Rs + (L + 96) * RSTRIDE;
    const float* rc0 = Rs + (L +  0);
    const float* rc1 = Rs + (L + 32);
    const float* rc2 = Rs + (L + 64);
    const float* rc3 = Rs + (L + 96);

    for (;;) {
        unsigned int task = next_task(0, L);
        if (task >= (unsigned)ntask) break;
        const int b = (int)(task >> 9);                 // 512 chunks per b
        const int sbase = ((int)task & 511) * TBA;
        const unsigned int base = ((unsigned)(b * HH) * SS + (unsigned)sbase) * DD;

        // ---- stage x: lane owns cols {L+32c}; coalesced LDG.32; 4-way STS ----
        float sq[TBA], nn[TBA], inv[TBA];
#pragma unroll
        for (int t = 0; t < TBA; t++) {
            float ssq = 0.f;
#pragma unroll
            for (int c = 0; c < 4; c++) {
                int j = L + 32 * c;
                float x = kv[base + t * DD + j];
                xs[j * XSA + t] = x;
                ssq += x * x;
            }
            sq[t] = ssq;
        }
#pragma unroll
        for (int t = 0; t < TBA; t++) {
            float tot = warp_sum(sq[t]);
            nn[t] = sqrtf(tot);
            inv[t] = 1.0f / (nn[t] + EPSF);
        }
        __syncwarp();

        unsigned long long acc[16];
        matvec8<1>(rr0, rr1, rr2, rr3, xs, acc);

        // ---- pass A: quantize + |res| accumulation ----
        float A[TBA];
#pragma unroll
        for (int t = 0; t < TBA; t++) A[t] = 0.f;
#pragma unroll
        for (int k = 0; k < 4; k++) {
#pragma unroll
            for (int p = 0; p < 4; p++) {
                float2 y = unpack2(acc[k * 4 + p]);
                float y0 = y.x * inv[2 * p], y1 = y.y * inv[2 * p + 1];
                float q0 = (y0 <= t1) ? ((y0 <= t0) ? c0 : c1) : ((y0 <= t2) ? c2 : c3);
                float q1 = (y1 <= t1) ? ((y1 <= t0) ? c0 : c1) : ((y1 <= t2) ? c2 : c3);
                A[2 * p]     += fabsf(y0 - q0);
                A[2 * p + 1] += fabsf(y1 - q1);
            }
        }
#pragma unroll
        for (int t = 0; t < TBA; t++) A[t] = warp_sum(A[t]) * (1.0f / 128.0f);  // alpha

        __syncwarp();   // matvec1 done reading xs warp-wide

        // ---- pass B: yhat -> xs ----
#pragma unroll
        for (int k = 0; k < 4; k++) {
            int i = L + 32 * k;
#pragma unroll
            for (int p = 0; p < 4; p++) {
                float2 y = unpack2(acc[k * 4 + p]);
#pragma unroll
                for (int h = 0; h < 2; h++) {
                    int t = 2 * p + h;
                    float yy = (h ? y.y : y.x) * inv[t];
                    float q = (yy <= t1) ? ((yy <= t0) ? c0 : c1) : ((yy <= t2) ? c2 : c3);
                    float res = yy - q;
                    float sg = (res > 0.f) ? 1.f : ((res < 0.f) ? -1.f : 0.f);
                    xs[i * XSA + t] = q + A[t] * sg;
                }
            }
        }
        __syncwarp();

        matvec8<RSTRIDE>(rc0, rc1, rc2, rc3, xs, acc);

        // ---- output ----
#pragma unroll
        for (int t = 0; t < TBA; t++) {
            int p = t >> 1;
#pragma unroll
            for (int k = 0; k < 4; k++) {
                float2 r = unpack2(acc[k * 4 + p]);
                float rv = (t & 1) ? r.y : r.x;
                out[base + t * DD + L + 32 * k] = rv * nn[t];
            }
        }
        __syncwarp();
    }
}

// ---------------- Phase 2: delta heads (PolarQuant), TB=16 ----------------
// Task = (16-token chunk, one head); head-minor task order so concurrent warps
// share the same anchor chunk in L2/L1.
__global__ void __launch_bounds__(NTHREAD, 1)
delta_kernel(const float* __restrict__ kv, const float* __restrict__ Rd,
             const float* __restrict__ cbd, const float* __restrict__ anc,
             float* __restrict__ out, int ntask) {
    extern __shared__ float sm[];
    float* Rs = sm;
    const int tid = threadIdx.x;
    const int w = tid >> 5, L = tid & 31;
    float* xs = sm + 128 * RSTRIDE + w * (128 * XSD);

    stage_R(Rs, Rd, tid);
    const float c0 = cbd[0], c1 = cbd[1];
    const float mid = 0.5f * (c0 + c1);
    __syncthreads();

    const float* rr0 = Rs + (L +  0) * RSTRIDE;
    const float* rr1 = Rs + (L + 32) * RSTRIDE;
    const float* rr2 = Rs + (L + 64) * RSTRIDE;
    const float* rr3 = Rs + (L + 96) * RSTRIDE;
    const float* rc0 = Rs + (L +  0);
    const float* rc1 = Rs + (L + 32);
    const float* rc2 = Rs + (L + 64);
    const float* rc3 = Rs + (L + 96);

    for (;;) {
        unsigned int task = next_task(1, L);
        if (task >= (unsigned)ntask) break;
        // head-minor: consecutive tasks = same chunk, different head
        const int chunk = (int)(task / 7);
        const int h = (int)(task - chunk * 7) + 1;
        const int b = chunk >> 8;                       // 256 chunks per b
        const int sbase = (chunk & 255) * TBD;
        const unsigned int kbase = ((unsigned)(b * HH + h) * SS + (unsigned)sbase) * DD;
        const unsigned int abase = ((unsigned)(b * HH) * SS + (unsigned)sbase) * DD;

        // ---- stage delta = kv - anchor; lane owns cols {L+32c}; coalesced ----
        float sq[TBD], nn[TBD], inv[TBD];
#pragma unroll
        for (int t = 0; t < TBD; t++) {
            float ssq = 0.f;
#pragma unroll
            for (int c = 0; c < 4; c++) {
                int j = L + 32 * c;
                float x = kv[kbase + t * DD + j] - anc[abase + t * DD + j];
                xs[j * XSD + t] = x;
                ssq += x * x;
            }
            sq[t] = ssq;
        }
#pragma unroll
        for (int t = 0; t < TBD; t++) {
            float tot = warp_sum(sq[t]);
            nn[t] = sqrtf(tot);
            inv[t] = 1.0f / (nn[t] + EPSF);
        }
        __syncwarp();

        unsigned long long acc[32];
        matvec16<1>(rr0, rr1, rr2, rr3, xs, acc);

        __syncwarp();   // all lanes done reading xs

        // ---- 1-bit polar quantize -> xs ----
#pragma unroll
        for (int k = 0; k < 4; k++) {
            int i = L + 32 * k;
#pragma unroll
            for (int p = 0; p < 8; p++) {
                float2 y = unpack2(acc[k * 8 + p]);
                float y0 = y.x * inv[2 * p], y1 = y.y * inv[2 * p + 1];
                xs[i * XSD + 2 * p]     = (y0 <= mid) ? c0 : c1;
                xs[i * XSD + 2 * p + 1] = (y1 <= mid) ? c0 : c1;
            }
        }
        __syncwarp();

        matvec16<RSTRIDE>(rc0, rc1, rc2, rc3, xs, acc);

        // ---- output: out = anchor + rec * norm (anchor reload: L1/L2 hit) ----
#pragma unroll
        for (int t = 0; t < TBD; t++) {
            int p = t >> 1;
#pragma unroll
            for (int k = 0; k < 4; k++) {
                float2 r = unpack2(acc[k * 8 + p]);
                float rv = (t & 1) ? r.y : r.x;
                int j = L + 32 * k;
                out[kbase + t * DD + j] = anc[abase + t * DD + j] + rv * nn[t];
            }
        }
        __syncwarp();
    }
}

extern "C" void kernel_launch(void* const* d_in, const int* in_sizes, int n_in,
                              void* d_out, int out_size) {
    const float* kv  = (const float*)d_in[0];
    const float* Ra  = (const float*)d_in[1];
    const float* cba = (const float*)d_in[2];
    const float* Rd  = (const float*)d_in[3];
    const float* cbd = (const float*)d_in[4];
    float* out = (float*)d_out;

    const int smem_a = SMEM_FLOATS_A * (int)sizeof(float);  // 139776
    const int smem_d = SMEM_FLOATS_D * (int)sizeof(float);  // 188928
    cudaFuncSetAttribute(anchor_kernel, cudaFuncAttributeMaxDynamicSharedMemorySize, smem_a);
    cudaFuncSetAttribute(delta_kernel,  cudaFuncAttributeMaxDynamicSharedMemorySize, smem_d);

    const int n_anchor_task = (BB * SS) / TBA;            // 4096
    const int n_delta_task  = (BB * SS) / TBD * 7;        // 2048 * 7 = 14336

    reset_kernel<<<1, 32>>>();
    anchor_kernel<<<NBLOCK, NTHREAD, smem_a>>>(kv, Ra, cba, out, n_anchor_task);
    delta_kernel <<<NBLOCK, NTHREAD, smem_d>>>(kv, Rd, cbd, out, out, n_delta_task);
}